// round 13
// baseline (speedup 1.0000x reference)
#include <cuda_runtime.h>
#include <math.h>

// ---------------------------------------------------------------------------
// AttentionLayer: B=64, L=R=512, H=512, D=256
//   T_lt[b,l,d] = tanh(lstm_lt @ W)[b,l,d] * diagW[d]
//   T_rt[b,r,d] = tanh(lstm_rt @ W)[b,r,d]
//   S[b,l,r]    = sum_d T_lt[b,l,d] * T_rt[b,r,d]
//   out         = softmax(S, axis=-1)
// Double-buffered smem tiling, 128x128x16 tiles, 8x8 per-thread microtile,
// packed fma.rn.f32x2 inner loop (per-row A dup: low register pressure),
// conflict-free B fragments (16B-aligned smem), fused lt+rt projection
// launch, warp-per-row softmax, outer loops unroll-capped (I$).
// DESIGN FROZEN pending first successful bench + ncu profile.
// ---------------------------------------------------------------------------

#define BDIM 64
#define LDIM 512
#define RDIM 512
#define HDIM 512
#define DDIM 256

#define TB 256
#define BM 128
#define BN 128
#define BK 16
#define TM 8
#define TN 8

#define MROWS 32768            // rows per projection (64*512)

typedef unsigned long long ull;

// Packed f32x2 FMA: d = a * b + c elementwise on two packed floats.
#define FMA_F32X2(d, a, b, c) \
    asm("fma.rn.f32x2 %0, %1, %2, %3;" : "=l"(d) : "l"(a), "l"(b), "l"(c))
// Broadcast one float into both lanes of a packed pair.
#define PACK_DUP(out, x) \
    asm("mov.b64 %0, {%1, %1};" : "=l"(out) : "f"(x))
// Unpack a packed pair into two floats.
#define UNPACK2(lo, hi, v) \
    asm("mov.b64 {%0, %1}, %2;" : "=f"(lo), "=f"(hi) : "l"(v))

// One microtile row: dup a into both lanes, 4 packed FMAs against bv0..3.
#define MICRO_ROW(acci, a_scalar) do {                     \
    ull _a2; PACK_DUP(_a2, a_scalar);                      \
    FMA_F32X2((acci)[0], _a2, bv0, (acci)[0]);             \
    FMA_F32X2((acci)[1], _a2, bv1, (acci)[1]);             \
    FMA_F32X2((acci)[2], _a2, bv2, (acci)[2]);             \
    FMA_F32X2((acci)[3], _a2, bv3, (acci)[3]);             \
} while (0)

__device__ __forceinline__ float fast_tanh(float x)
{
    float y;
    asm("tanh.approx.f32 %0, %1;" : "=f"(y) : "f"(x));
    return y;
}

__device__ __forceinline__ float fast_rcp(float x)
{
    float y;
    asm("rcp.approx.f32 %0, %1;" : "=f"(y) : "f"(x));
    return y;
}

// Scratch: both projection outputs in one array (lt rows [0,32768),
// rt rows [32768,65536)), 67 MB, static device allocation.
__device__ float g_T[(size_t)2 * MROWS * DDIM];

// ---------------------------------------------------------------------------
// Fused projection GEMM (NN) over combined M = 65536:
//   rows [0, 32768)      : C = tanh(lstm_lt @ W) * diagW
//   rows [32768, 65536)  : C = tanh(lstm_rt @ W)
// W: 512 x 256 row-major.
// ---------------------------------------------------------------------------
__global__ __launch_bounds__(TB, 2)
void proj_kernel(const float* __restrict__ Alt, const float* __restrict__ Art,
                 const float* __restrict__ W, const float* __restrict__ dW,
                 float* __restrict__ C)
{
    const int K = HDIM, N = DDIM;
    // __align__(16): LDS.128 reads require 16B-aligned base (err715 otherwise).
    __shared__ __align__(16) float As[2][BK][BM + 4];   // transposed A tile
    __shared__ __align__(16) float Bs[2][BK][BN];       // B tile, natural layout

    const int bm = blockIdx.y * BM;       // global row in [0, 65536)
    const bool isLt = (bm < MROWS);
    const float* __restrict__ A = isLt ? Alt : Art;
    const int bmLocal = isLt ? bm : (bm - MROWS);

    const int bn = blockIdx.x * BN;
    const int tid = threadIdx.x;
    const int tx = tid % 16;              // 16 x 16 thread grid
    const int ty = tid / 16;

    // Per-thread load coordinates (fixed across iterations).
    const int a_row0 = (tid + 0 * TB) >> 2;
    const int a_kq0  = ((tid + 0 * TB) & 3) * 4;
    const int a_row1 = (tid + 1 * TB) >> 2;
    const int a_kq1  = ((tid + 1 * TB) & 3) * 4;
    const int b_row0 = (tid + 0 * TB) >> 5;
    const int b_c40  = ((tid + 0 * TB) & 31) * 4;
    const int b_row1 = (tid + 1 * TB) >> 5;
    const int b_c41  = ((tid + 1 * TB) & 31) * 4;

    const float* __restrict__ pA0 = &A[(size_t)(bmLocal + a_row0) * K];
    const float* __restrict__ pA1 = &A[(size_t)(bmLocal + a_row1) * K];

    // Accumulators: 8 rows x 4 packed column-pairs.
    ull acc2[TM][4];
    #pragma unroll
    for (int i = 0; i < TM; i++)
        #pragma unroll
        for (int j = 0; j < 4; j++) acc2[i][j] = 0ull;

    // ---- prologue: load tile 0 into buffer 0 ----
    {
        float4 va0 = *reinterpret_cast<const float4*>(&pA0[a_kq0]);
        float4 va1 = *reinterpret_cast<const float4*>(&pA1[a_kq1]);
        float4 vb0 = *reinterpret_cast<const float4*>(&W[(size_t)(b_row0) * N + bn + b_c40]);
        float4 vb1 = *reinterpret_cast<const float4*>(&W[(size_t)(b_row1) * N + bn + b_c41]);
        As[0][a_kq0 + 0][a_row0] = va0.x; As[0][a_kq0 + 1][a_row0] = va0.y;
        As[0][a_kq0 + 2][a_row0] = va0.z; As[0][a_kq0 + 3][a_row0] = va0.w;
        As[0][a_kq1 + 0][a_row1] = va1.x; As[0][a_kq1 + 1][a_row1] = va1.y;
        As[0][a_kq1 + 2][a_row1] = va1.z; As[0][a_kq1 + 3][a_row1] = va1.w;
        *reinterpret_cast<float4*>(&Bs[0][b_row0][b_c40]) = vb0;
        *reinterpret_cast<float4*>(&Bs[0][b_row1][b_c41]) = vb1;
    }
    __syncthreads();

    const int NT = K / BK;   // 32 tiles
    #pragma unroll 2         // cap unroll: I$-safe, static cur/nxt
    for (int kt = 0; kt < NT; kt++) {
        const int cur = kt & 1;
        const int nxt = cur ^ 1;

        // Issue next tile's global loads FIRST (latency overlapped with compute).
        float4 va0, va1, vb0, vb1;
        if (kt + 1 < NT) {
            const int k0 = (kt + 1) * BK;
            va0 = *reinterpret_cast<const float4*>(&pA0[k0 + a_kq0]);
            va1 = *reinterpret_cast<const float4*>(&pA1[k0 + a_kq1]);
            vb0 = *reinterpret_cast<const float4*>(&W[(size_t)(k0 + b_row0) * N + bn + b_c40]);
            vb1 = *reinterpret_cast<const float4*>(&W[(size_t)(k0 + b_row1) * N + bn + b_c41]);
        }

        // Compute on current buffer; packed f32x2 FMAs, per-row A dup.
        #pragma unroll
        for (int k = 0; k < BK; k++) {
            float4 a0 = *reinterpret_cast<const float4*>(&As[cur][k][ty * TM]);
            float4 a1 = *reinterpret_cast<const float4*>(&As[cur][k][ty * TM + 4]);
            // B fragments: adjacent-paired in smem, read as packed 64-bit pairs.
            ulonglong2 bp0 = *reinterpret_cast<const ulonglong2*>(&Bs[cur][k][tx * 4]);
            ulonglong2 bp1 = *reinterpret_cast<const ulonglong2*>(&Bs[cur][k][64 + tx * 4]);
            const ull bv0 = bp0.x, bv1 = bp0.y, bv2 = bp1.x, bv3 = bp1.y;
            MICRO_ROW(acc2[0], a0.x);
            MICRO_ROW(acc2[1], a0.y);
            MICRO_ROW(acc2[2], a0.z);
            MICRO_ROW(acc2[3], a0.w);
            MICRO_ROW(acc2[4], a1.x);
            MICRO_ROW(acc2[5], a1.y);
            MICRO_ROW(acc2[6], a1.z);
            MICRO_ROW(acc2[7], a1.w);
        }

        // Stage next tile into the other buffer.
        if (kt + 1 < NT) {
            As[nxt][a_kq0 + 0][a_row0] = va0.x; As[nxt][a_kq0 + 1][a_row0] = va0.y;
            As[nxt][a_kq0 + 2][a_row0] = va0.z; As[nxt][a_kq0 + 3][a_row0] = va0.w;
            As[nxt][a_kq1 + 0][a_row1] = va1.x; As[nxt][a_kq1 + 1][a_row1] = va1.y;
            As[nxt][a_kq1 + 2][a_row1] = va1.z; As[nxt][a_kq1 + 3][a_row1] = va1.w;
            *reinterpret_cast<float4*>(&Bs[nxt][b_row0][b_c40]) = vb0;
            *reinterpret_cast<float4*>(&Bs[nxt][b_row1][b_c41]) = vb1;
        }
        __syncthreads();
    }

    // Epilogue: columns bn+tx*4+{0..3} and bn+64+tx*4+{0..3}.
    const int c0 = bn + tx * 4;
    const int c1 = bn + 64 + tx * 4;
    float d0x=1.f, d0y=1.f, d0z=1.f, d0w=1.f, d1x=1.f, d1y=1.f, d1z=1.f, d1w=1.f;
    if (isLt) {
        float4 dv0 = *reinterpret_cast<const float4*>(&dW[c0]);
        float4 dv1 = *reinterpret_cast<const float4*>(&dW[c1]);
        d0x=dv0.x; d0y=dv0.y; d0z=dv0.z; d0w=dv0.w;
        d1x=dv1.x; d1y=dv1.y; d1z=dv1.z; d1w=dv1.w;
    }
    #pragma unroll
    for (int i = 0; i < TM; i++) {
        const int m = bm + ty * TM + i;   // global row (lt or rt half)
        float s0, s1, s2, s3, s4, s5, s6, s7;
        UNPACK2(s0, s1, acc2[i][0]);
        UNPACK2(s2, s3, acc2[i][1]);
        UNPACK2(s4, s5, acc2[i][2]);
        UNPACK2(s6, s7, acc2[i][3]);
        float4 o0, o1;
        o0.x = fast_tanh(s0) * d0x;
        o0.y = fast_tanh(s1) * d0y;
        o0.z = fast_tanh(s2) * d0z;
        o0.w = fast_tanh(s3) * d0w;
        o1.x = fast_tanh(s4) * d1x;
        o1.y = fast_tanh(s5) * d1y;
        o1.z = fast_tanh(s6) * d1z;
        o1.w = fast_tanh(s7) * d1w;
        *reinterpret_cast<float4*>(&C[(size_t)m * N + c0]) = o0;
        *reinterpret_cast<float4*>(&C[(size_t)m * N + c1]) = o1;
    }
}

// ---------------------------------------------------------------------------
// GEMM 3 (NT): per batch b, S[l,r] = sum_d Tlt[l,d] * Trt[r,d].
// Tlt = g_T rows [b*512, b*512+512); Trt = g_T rows [32768 + b*512, ...).
// ---------------------------------------------------------------------------
__global__ __launch_bounds__(TB, 2)
void score_kernel(float* __restrict__ out)
{
    const int K = DDIM;
    const float* __restrict__ Ab = g_T + (size_t)blockIdx.z * LDIM * DDIM;
    const float* __restrict__ Bb = g_T + ((size_t)MROWS + (size_t)blockIdx.z * RDIM) * DDIM;

    __shared__ __align__(16) float As[2][BK][BM + 4];
    __shared__ __align__(16) float Bs[2][BK][BN + 4];

    const int bm = blockIdx.y * BM;
    const int bn = blockIdx.x * BN;
    const int tid = threadIdx.x;
    const int tx = tid % 16;
    const int ty = tid / 16;

    const int r0 = (tid + 0 * TB) >> 2;
    const int q0 = ((tid + 0 * TB) & 3) * 4;
    const int r1 = (tid + 1 * TB) >> 2;
    const int q1 = ((tid + 1 * TB) & 3) * 4;

    const float* __restrict__ pA0 = &Ab[(size_t)(bm + r0) * K];
    const float* __restrict__ pA1 = &Ab[(size_t)(bm + r1) * K];
    const float* __restrict__ pB0 = &Bb[(size_t)(bn + r0) * K];
    const float* __restrict__ pB1 = &Bb[(size_t)(bn + r1) * K];

    ull acc2[TM][4];
    #pragma unroll
    for (int i = 0; i < TM; i++)
        #pragma unroll
        for (int j = 0; j < 4; j++) acc2[i][j] = 0ull;

    // ---- prologue: tile 0 -> buffer 0 ----
    {
        float4 va0 = *reinterpret_cast<const float4*>(&pA0[q0]);
        float4 va1 = *reinterpret_cast<const float4*>(&pA1[q1]);
        float4 vb0 = *reinterpret_cast<const float4*>(&pB0[q0]);
        float4 vb1 = *reinterpret_cast<const float4*>(&pB1[q1]);
        As[0][q0 + 0][r0] = va0.x; As[0][q0 + 1][r0] = va0.y;
        As[0][q0 + 2][r0] = va0.z; As[0][q0 + 3][r0] = va0.w;
        As[0][q1 + 0][r1] = va1.x; As[0][q1 + 1][r1] = va1.y;
        As[0][q1 + 2][r1] = va1.z; As[0][q1 + 3][r1] = va1.w;
        Bs[0][q0 + 0][r0] = vb0.x; Bs[0][q0 + 1][r0] = vb0.y;
        Bs[0][q0 + 2][r0] = vb0.z; Bs[0][q0 + 3][r0] = vb0.w;
        Bs[0][q1 + 0][r1] = vb1.x; Bs[0][q1 + 1][r1] = vb1.y;
        Bs[0][q1 + 2][r1] = vb1.z; Bs[0][q1 + 3][r1] = vb1.w;
    }
    __syncthreads();

    const int NT = K / BK;   // 16 tiles
    #pragma unroll 2         // cap unroll: I$-safe, static cur/nxt
    for (int kt = 0; kt < NT; kt++) {
        const int cur = kt & 1;
        const int nxt = cur ^ 1;

        float4 va0, va1, vb0q, vb1q;
        if (kt + 1 < NT) {
            const int k0 = (kt + 1) * BK;
            va0  = *reinterpret_cast<const float4*>(&pA0[k0 + q0]);
            va1  = *reinterpret_cast<const float4*>(&pA1[k0 + q1]);
            vb0q = *reinterpret_cast<const float4*>(&pB0[k0 + q0]);
            vb1q = *reinterpret_cast<const float4*>(&pB1[k0 + q1]);
        }

        #pragma unroll
        for (int k = 0; k < BK; k++) {
            float4 a0 = *reinterpret_cast<const float4*>(&As[cur][k][ty * TM]);
            float4 a1 = *reinterpret_cast<const float4*>(&As[cur][k][ty * TM + 4]);
            ulonglong2 bp0 = *reinterpret_cast<const ulonglong2*>(&Bs[cur][k][tx * 4]);
            ulonglong2 bp1 = *reinterpret_cast<const ulonglong2*>(&Bs[cur][k][64 + tx * 4]);
            const ull bv0 = bp0.x, bv1 = bp0.y, bv2 = bp1.x, bv3 = bp1.y;
            MICRO_ROW(acc2[0], a0.x);
            MICRO_ROW(acc2[1], a0.y);
            MICRO_ROW(acc2[2], a0.z);
            MICRO_ROW(acc2[3], a0.w);
            MICRO_ROW(acc2[4], a1.x);
            MICRO_ROW(acc2[5], a1.y);
            MICRO_ROW(acc2[6], a1.z);
            MICRO_ROW(acc2[7], a1.w);
        }

        if (kt + 1 < NT) {
            As[nxt][q0 + 0][r0] = va0.x; As[nxt][q0 + 1][r0] = va0.y;
            As[nxt][q0 + 2][r0] = va0.z; As[nxt][q0 + 3][r0] = va0.w;
            As[nxt][q1 + 0][r1] = va1.x; As[nxt][q1 + 1][r1] = va1.y;
            As[nxt][q1 + 2][r1] = va1.z; As[nxt][q1 + 3][r1] = va1.w;
            Bs[nxt][q0 + 0][r0] = vb0q.x; Bs[nxt][q0 + 1][r0] = vb0q.y;
            Bs[nxt][q0 + 2][r0] = vb0q.z; Bs[nxt][q0 + 3][r0] = vb0q.w;
            Bs[nxt][q1 + 0][r1] = vb1q.x; Bs[nxt][q1 + 1][r1] = vb1q.y;
            Bs[nxt][q1 + 2][r1] = vb1q.z; Bs[nxt][q1 + 3][r1] = vb1q.w;
        }
        __syncthreads();
    }

    float* Cb = out + (size_t)blockIdx.z * LDIM * RDIM;
    const int c0 = bn + tx * 4;
    const int c1 = bn + 64 + tx * 4;
    #pragma unroll
    for (int i = 0; i < TM; i++) {
        const int m = bm + ty * TM + i;
        float4 o0, o1;
        UNPACK2(o0.x, o0.y, acc2[i][0]);
        UNPACK2(o0.z, o0.w, acc2[i][1]);
        UNPACK2(o1.x, o1.y, acc2[i][2]);
        UNPACK2(o1.z, o1.w, acc2[i][3]);
        *reinterpret_cast<float4*>(&Cb[(size_t)m * RDIM + c0]) = o0;
        *reinterpret_cast<float4*>(&Cb[(size_t)m * RDIM + c1]) = o1;
    }
}

// ---------------------------------------------------------------------------
// In-place row softmax over R=512, one WARP per row (no smem, no barriers).
// Block = 256 threads = 8 warps = 8 rows; each lane owns 16 elements as
// 4 coalesced float4 loads.
// ---------------------------------------------------------------------------
__global__ __launch_bounds__(256)
void softmax_kernel(float* __restrict__ data)
{
    const int warp = threadIdx.x >> 5;
    const int lid  = threadIdx.x & 31;
    float4* row4 = reinterpret_cast<float4*>(
        data + ((size_t)blockIdx.x * 8 + warp) * RDIM);

    // Load 4 float4 per lane (front-batched, MLP=4).
    float4 v0 = row4[lid];
    float4 v1 = row4[lid + 32];
    float4 v2 = row4[lid + 64];
    float4 v3 = row4[lid + 96];

    // --- max reduce (warp-local) ---
    float m = fmaxf(fmaxf(fmaxf(v0.x, v0.y), fmaxf(v0.z, v0.w)),
                    fmaxf(fmaxf(v1.x, v1.y), fmaxf(v1.z, v1.w)));
    m = fmaxf(m, fmaxf(fmaxf(fmaxf(v2.x, v2.y), fmaxf(v2.z, v2.w)),
                       fmaxf(fmaxf(v3.x, v3.y), fmaxf(v3.z, v3.w))));
    #pragma unroll
    for (int o = 16; o; o >>= 1) m = fmaxf(m, __shfl_xor_sync(0xffffffffu, m, o));

    // --- exp + sum reduce ---
    v0.x = __expf(v0.x - m); v0.y = __expf(v0.y - m);
    v0.z = __expf(v0.z - m); v0.w = __expf(v0.w - m);
    v1.x = __expf(v1.x - m); v1.y = __expf(v1.y - m);
    v1.z = __expf(v1.z - m); v1.w = __expf(v1.w - m);
    v2.x = __expf(v2.x - m); v2.y = __expf(v2.y - m);
    v2.z = __expf(v2.z - m); v2.w = __expf(v2.w - m);
    v3.x = __expf(v3.x - m); v3.y = __expf(v3.y - m);
    v3.z = __expf(v3.z - m); v3.w = __expf(v3.w - m);

    float s = (v0.x + v0.y + v0.z + v0.w) + (v1.x + v1.y + v1.z + v1.w)
            + (v2.x + v2.y + v2.z + v2.w) + (v3.x + v3.y + v3.z + v3.w);
    #pragma unroll
    for (int o = 16; o; o >>= 1) s += __shfl_xor_sync(0xffffffffu, s, o);
    const float inv = fast_rcp(s);   // MUFU.RCP, rel err ~2^-22 << 1e-3

    v0.x *= inv; v0.y *= inv; v0.z *= inv; v0.w *= inv;
    v1.x *= inv; v1.y *= inv; v1.z *= inv; v1.w *= inv;
    v2.x *= inv; v2.y *= inv; v2.z *= inv; v2.w *= inv;
    v3.x *= inv; v3.y *= inv; v3.z *= inv; v3.w *= inv;

    row4[lid]      = v0;
    row4[lid + 32] = v1;
    row4[lid + 64] = v2;
    row4[lid + 96] = v3;
}

// ---------------------------------------------------------------------------
extern "C" void kernel_launch(void* const* d_in, const int* in_sizes, int n_in,
                              void* d_out, int out_size)
{
    const float* lstm_lt = (const float*)d_in[0];   // (64, 512, 512)
    const float* lstm_rt = (const float*)d_in[1];   // (64, 512, 512)
    const float* atten_W = (const float*)d_in[2];   // (512, 256)
    const float* diag_W  = (const float*)d_in[3];   // (1, 1, 256)
    float* out = (float*)d_out;                     // (64, 512, 512)

    void* pT = nullptr;
    cudaGetSymbolAddress(&pT, g_T);

    // Fused projections: combined M = 65536 rows, N = 256, K = 512.
    {
        dim3 grid(DDIM / BN, (2 * MROWS) / BM);     // (2, 512)
        proj_kernel<<<grid, TB>>>(lstm_lt, lstm_rt, atten_W, diag_W, (float*)pT);
    }

    // Scores: per-batch 512x512x256 NT GEMM.
    {
        dim3 grid(RDIM / BN, LDIM / BM, BDIM);      // (4, 4, 64)
        score_kernel<<<grid, TB>>>(out);
    }

    // Softmax in-place: one warp per row, 8 rows per block.
    softmax_kernel<<<(BDIM * LDIM) / 8, 256>>>(out);
}